// round 7
// baseline (speedup 1.0000x reference)
#include <cuda_runtime.h>
#include <math.h>
#include <string.h>

#define IMG_H 512
#define IMG_W 512
#define N_IMG 32
#define WS 11
#define HALO 5
#define TS 32
#define TW (TS + 2*HALO)   // 42
#define SPITCH 44          // padded pitch for s1/s2 (float4-aligned rows)
#define HPITCH 34          // padded pitch for h (kills 128B-aligned bank conflicts)
#define NPART 512

typedef unsigned long long ull;

struct WPack { ull ww[WS]; };   // (w[k], w[k]) packed f32x2, computed on host in double

__device__ unsigned g_pmin[NPART];
__device__ unsigned g_pmax[NPART];

__device__ __forceinline__ unsigned encf(float f) {
    unsigned u = __float_as_uint(f);
    return (u & 0x80000000u) ? ~u : (u | 0x80000000u);
}
__device__ __forceinline__ float decf(unsigned u) {
    u = (u & 0x80000000u) ? (u & 0x7fffffffu) : ~u;
    return __uint_as_float(u);
}

// ---- packed f32x2 helpers (FFMA2 only reachable via PTX) ----
__device__ __forceinline__ ull ffma2(ull a, ull b, ull c) {
    ull d; asm("fma.rn.f32x2 %0, %1, %2, %3;" : "=l"(d) : "l"(a), "l"(b), "l"(c)); return d;
}
__device__ __forceinline__ ull fmul2(ull a, ull b) {
    ull d; asm("mul.rn.f32x2 %0, %1, %2;" : "=l"(d) : "l"(a), "l"(b)); return d;
}
__device__ __forceinline__ ull pk2(float lo, float hi) {
    ull d; asm("mov.b64 %0, {%1, %2};" : "=l"(d) : "f"(lo), "f"(hi)); return d;
}
__device__ __forceinline__ float2 upk(ull v) {
    float2 r; asm("mov.b64 {%0, %1}, %2;" : "=f"(r.x), "=f"(r.y) : "l"(v)); return r;
}

__global__ __launch_bounds__(256)
void minmax_kernel(const float* __restrict__ x, int n4) {
    unsigned mn = 0xFFFFFFFFu, mx = 0u;
    const float4* x4 = (const float4*)x;
    for (int i = blockIdx.x * blockDim.x + threadIdx.x; i < n4;
         i += gridDim.x * blockDim.x) {
        float4 v = x4[i];
        unsigned e0 = encf(v.x), e1 = encf(v.y), e2 = encf(v.z), e3 = encf(v.w);
        mn = min(mn, min(min(e0, e1), min(e2, e3)));
        mx = max(mx, max(max(e0, e1), max(e2, e3)));
    }
    #pragma unroll
    for (int off = 16; off > 0; off >>= 1) {
        mn = min(mn, __shfl_xor_sync(0xFFFFFFFFu, mn, off));
        mx = max(mx, __shfl_xor_sync(0xFFFFFFFFu, mx, off));
    }
    __shared__ unsigned smn[8], smx[8];
    int wid = threadIdx.x >> 5, lid = threadIdx.x & 31;
    if (lid == 0) { smn[wid] = mn; smx[wid] = mx; }
    __syncthreads();
    if (threadIdx.x == 0) {
        unsigned bmn = smn[0], bmx = smx[0];
        #pragma unroll
        for (int i = 1; i < 8; i++) { bmn = min(bmn, smn[i]); bmx = max(bmx, smx[i]); }
        g_pmin[blockIdx.x] = bmn;
        g_pmax[blockIdx.x] = bmx;
    }
}

__global__ __launch_bounds__(256, 2)
void ssim_kernel(const float* __restrict__ img1, const float* __restrict__ img2,
                 float* __restrict__ out, WPack wp) {
    __shared__ float s1[TW][SPITCH];
    __shared__ float s2[TW][SPITCH];
    __shared__ float h[5][TW][HPITCH];
    __shared__ unsigned red_mn[8], red_mx[8];

    const int n = blockIdx.z;
    const int x0 = blockIdx.x * TS;
    const int y0 = blockIdx.y * TS;
    const int tid = threadIdx.x;

    // cache packed weights in registers (avoid per-use LDC, floor=8)
    ull W[WS];
    #pragma unroll
    for (int k = 0; k < WS; k++) W[k] = wp.ww[k];

    // ---- global min/max: reduce 512 L2-hot partials ----
    {
        unsigned mn = min(g_pmin[tid], g_pmin[tid + 256]);
        unsigned mx = max(g_pmax[tid], g_pmax[tid + 256]);
        #pragma unroll
        for (int off = 16; off > 0; off >>= 1) {
            mn = min(mn, __shfl_xor_sync(0xFFFFFFFFu, mn, off));
            mx = max(mx, __shfl_xor_sync(0xFFFFFFFFu, mx, off));
        }
        if ((tid & 31) == 0) { red_mn[tid >> 5] = mn; red_mx[tid >> 5] = mx; }
    }

    const float* p1 = img1 + (size_t)n * IMG_H * IMG_W;
    const float* p2 = img2 + (size_t)n * IMG_H * IMG_W;

    // ---- load raw tiles with halo ----
    const bool interior = (x0 >= HALO) & (x0 + TS + HALO <= IMG_W) &
                          (y0 >= HALO) & (y0 + TS + HALO <= IMG_H);
    if (interior) {
        const float* q1 = p1 + (size_t)(y0 - HALO) * IMG_W + (x0 - HALO);
        const float* q2 = p2 + (size_t)(y0 - HALO) * IMG_W + (x0 - HALO);
        #pragma unroll 1
        for (int idx = tid; idx < TW * TW; idx += 256) {
            int r = idx / TW, c = idx - r * TW;
            s1[r][c] = __ldg(q1 + r * IMG_W + c);
            s2[r][c] = __ldg(q2 + r * IMG_W + c);
        }
    } else {
        #pragma unroll 1
        for (int idx = tid; idx < TW * TW; idx += 256) {
            int r = idx / TW, c = idx - r * TW;
            int gy = y0 + r - HALO, gx = x0 + c - HALO;
            bool in = (gy >= 0) & (gy < IMG_H) & (gx >= 0) & (gx < IMG_W);
            float a = 0.f, b = 0.f;
            if (in) {
                size_t o = (size_t)gy * IMG_W + gx;
                a = __ldg(p1 + o);
                b = __ldg(p2 + o);
            }
            s1[r][c] = a;
            s2[r][c] = b;
        }
    }
    __syncthreads();

    // ---- horizontal pass: 4 outputs per item as 2 packed pairs ----
    #pragma unroll 1
    for (int item = tid; item < TW * 8; item += 256) {
        int r = item >> 3;
        int c0 = (item & 7) << 2;
        float A[16], B[16];
        #pragma unroll
        for (int j = 0; j < 4; j++) {
            float4 va = *(const float4*)&s1[r][c0 + 4 * j];
            float4 vb = *(const float4*)&s2[r][c0 + 4 * j];
            A[4*j+0] = va.x; A[4*j+1] = va.y; A[4*j+2] = va.z; A[4*j+3] = va.w;
            B[4*j+0] = vb.x; B[4*j+1] = vb.y; B[4*j+2] = vb.z; B[4*j+3] = vb.w;
        }
        ull a0 = 0, a1 = 0, a2 = 0, a3 = 0, a4 = 0;   // pair (c0, c0+1)
        ull b0 = 0, b1 = 0, b2 = 0, b3 = 0, b4 = 0;   // pair (c0+2, c0+3)
        #pragma unroll
        for (int i = 0; i < 13; i++) {
            ull pa  = pk2(A[i], A[i + 1]);
            ull pb  = pk2(B[i], B[i + 1]);
            ull paa = fmul2(pa, pa);
            ull pbb = fmul2(pb, pb);
            ull pab = fmul2(pa, pb);
            if (i <= 10) {
                ull w = W[i];
                a0 = ffma2(pa,  w, a0);
                a1 = ffma2(pb,  w, a1);
                a2 = ffma2(paa, w, a2);
                a3 = ffma2(pbb, w, a3);
                a4 = ffma2(pab, w, a4);
            }
            if (i >= 2) {
                ull w = W[i - 2];
                b0 = ffma2(pa,  w, b0);
                b1 = ffma2(pb,  w, b1);
                b2 = ffma2(paa, w, b2);
                b3 = ffma2(pbb, w, b3);
                b4 = ffma2(pab, w, b4);
            }
        }
        *(ull*)&h[0][r][c0]     = a0;  *(ull*)&h[0][r][c0 + 2] = b0;
        *(ull*)&h[1][r][c0]     = a1;  *(ull*)&h[1][r][c0 + 2] = b1;
        *(ull*)&h[2][r][c0]     = a2;  *(ull*)&h[2][r][c0 + 2] = b2;
        *(ull*)&h[3][r][c0]     = a3;  *(ull*)&h[3][r][c0 + 2] = b3;
        *(ull*)&h[4][r][c0]     = a4;  *(ull*)&h[4][r][c0 + 2] = b4;
    }
    __syncthreads();

    // ---- constants from reduced min/max ----
    float C1, C2;
    {
        unsigned bmn = red_mn[0], bmx = red_mx[0];
        #pragma unroll
        for (int i = 1; i < 8; i++) { bmn = min(bmn, red_mn[i]); bmx = max(bmx, red_mx[i]); }
        float L = decf(bmx) - decf(bmn);
        if (L == 0.f) L = 5.f;
        C1 = (0.01f * L) * (0.01f * L);
        C2 = (0.03f * L) * (0.03f * L);
    }

    // ---- vertical pass: 2 rows x 2 packed cols per thread ----
    const int tx2 = (tid & 15) << 1;   // col pair 0..30
    const int ty0 = (tid >> 4) << 1;   // row pair 0..30
    ull m0 = 0, m1 = 0, m2 = 0, m3 = 0, m4 = 0;   // row ty0
    ull n0 = 0, n1 = 0, n2 = 0, n3 = 0, n4 = 0;   // row ty0+1
    #pragma unroll
    for (int i = 0; i < 12; i++) {
        ull v0 = *(const ull*)&h[0][ty0 + i][tx2];
        ull v1 = *(const ull*)&h[1][ty0 + i][tx2];
        ull v2 = *(const ull*)&h[2][ty0 + i][tx2];
        ull v3 = *(const ull*)&h[3][ty0 + i][tx2];
        ull v4 = *(const ull*)&h[4][ty0 + i][tx2];
        if (i <= 10) {
            ull w = W[i];
            m0 = ffma2(v0, w, m0);
            m1 = ffma2(v1, w, m1);
            m2 = ffma2(v2, w, m2);
            m3 = ffma2(v3, w, m3);
            m4 = ffma2(v4, w, m4);
        }
        if (i >= 1) {
            ull w = W[i - 1];
            n0 = ffma2(v0, w, n0);
            n1 = ffma2(v1, w, n1);
            n2 = ffma2(v2, w, n2);
            n3 = ffma2(v3, w, n3);
            n4 = ffma2(v4, w, n4);
        }
    }

    float* po = out + (size_t)n * IMG_H * IMG_W + (size_t)(y0 + ty0) * IMG_W + (x0 + tx2);

    // row 0
    {
        float2 u1 = upk(m0), u2 = upk(m1), uq1 = upk(m2), uq2 = upk(m3), uq12 = upk(m4);
        float2 res;
        {
            float mu1s = u1.x * u1.x, mu2s = u2.x * u2.x, mu12 = u1.x * u2.x;
            float sg1 = uq1.x - mu1s, sg2 = uq2.x - mu2s, sg12 = uq12.x - mu12;
            res.x = __fdividef((2.f * mu12 + C1) * (2.f * sg12 + C2),
                               (mu1s + mu2s + C1) * (sg1 + sg2 + C2));
        }
        {
            float mu1s = u1.y * u1.y, mu2s = u2.y * u2.y, mu12 = u1.y * u2.y;
            float sg1 = uq1.y - mu1s, sg2 = uq2.y - mu2s, sg12 = uq12.y - mu12;
            res.y = __fdividef((2.f * mu12 + C1) * (2.f * sg12 + C2),
                               (mu1s + mu2s + C1) * (sg1 + sg2 + C2));
        }
        *(float2*)po = res;
    }
    // row 1
    {
        float2 u1 = upk(n0), u2 = upk(n1), uq1 = upk(n2), uq2 = upk(n3), uq12 = upk(n4);
        float2 res;
        {
            float mu1s = u1.x * u1.x, mu2s = u2.x * u2.x, mu12 = u1.x * u2.x;
            float sg1 = uq1.x - mu1s, sg2 = uq2.x - mu2s, sg12 = uq12.x - mu12;
            res.x = __fdividef((2.f * mu12 + C1) * (2.f * sg12 + C2),
                               (mu1s + mu2s + C1) * (sg1 + sg2 + C2));
        }
        {
            float mu1s = u1.y * u1.y, mu2s = u2.y * u2.y, mu12 = u1.y * u2.y;
            float sg1 = uq1.y - mu1s, sg2 = uq2.y - mu2s, sg12 = uq12.y - mu12;
            res.y = __fdividef((2.f * mu12 + C1) * (2.f * sg12 + C2),
                               (mu1s + mu2s + C1) * (sg1 + sg2 + C2));
        }
        *(float2*)(po + IMG_W) = res;
    }
}

extern "C" void kernel_launch(void* const* d_in, const int* in_sizes, int n_in,
                              void* d_out, int out_size) {
    const float* img1 = (const float*)d_in[0];
    const float* img2 = (const float*)d_in[1];
    float* out = (float*)d_out;

    // Gaussian taps, center at ws/2 = 5.5 (torch quirk), double precision
    WPack wp;
    {
        double g[WS], s = 0.0;
        for (int i = 0; i < WS; i++) {
            double d = (double)i - (double)WS / 2.0;
            g[i] = exp(-(d * d) / (2.0 * 1.5 * 1.5));
            s += g[i];
        }
        for (int i = 0; i < WS; i++) {
            float f = (float)(g[i] / s);
            unsigned u;
            memcpy(&u, &f, 4);
            wp.ww[i] = (ull)u | ((ull)u << 32);
        }
    }

    int n_elems = N_IMG * IMG_H * IMG_W;
    minmax_kernel<<<NPART, 256>>>(img1, n_elems / 4);

    dim3 grid(IMG_W / TS, IMG_H / TS, N_IMG);
    ssim_kernel<<<grid, 256>>>(img1, img2, out, wp);
}

// round 10
// speedup vs baseline: 1.7387x; 1.7387x over previous
#include <cuda_runtime.h>

#define IMG_H 512
#define IMG_W 512
#define N_IMG 32
#define WS 11
#define HALO 5
#define TS 32
#define TW 42
#define NPART 512

// Gaussian taps, center at ws/2 = 5.5 (torch quirk): symmetric pairs 1<->10 .. 5<->6, w0 unique
#define W0 0.00032030f
#define W1 0.00295565f
#define W2 0.01748763f
#define W3 0.06634246f
#define W4 0.16137298f
#define W5 0.25168106f

__device__ __forceinline__ float wk_of(int k) {
    // k is compile-time under full unroll -> immediate-form FFMA (rt=1)
    switch (k) {
        case 0: return W0; case 1: return W1; case 2: return W2;
        case 3: return W3; case 4: return W4; case 5: return W5;
        case 6: return W5; case 7: return W4; case 8: return W3;
        case 9: return W2; default: return W1;
    }
}

__device__ unsigned g_pmin[NPART];
__device__ unsigned g_pmax[NPART];

__device__ __forceinline__ unsigned encf(float f) {
    unsigned u = __float_as_uint(f);
    return (u & 0x80000000u) ? ~u : (u | 0x80000000u);
}
__device__ __forceinline__ float decf(unsigned u) {
    u = (u & 0x80000000u) ? (u & 0x7fffffffu) : ~u;
    return __uint_as_float(u);
}

__global__ __launch_bounds__(256)
void minmax_kernel(const float* __restrict__ x, int n4) {
    unsigned mn = 0xFFFFFFFFu, mx = 0u;
    const float4* x4 = (const float4*)x;
    for (int i = blockIdx.x * blockDim.x + threadIdx.x; i < n4;
         i += gridDim.x * blockDim.x) {
        float4 v = x4[i];
        unsigned e0 = encf(v.x), e1 = encf(v.y), e2 = encf(v.z), e3 = encf(v.w);
        mn = min(mn, min(min(e0, e1), min(e2, e3)));
        mx = max(mx, max(max(e0, e1), max(e2, e3)));
    }
    #pragma unroll
    for (int off = 16; off > 0; off >>= 1) {
        mn = min(mn, __shfl_xor_sync(0xFFFFFFFFu, mn, off));
        mx = max(mx, __shfl_xor_sync(0xFFFFFFFFu, mx, off));
    }
    __shared__ unsigned smn[8], smx[8];
    int wid = threadIdx.x >> 5, lid = threadIdx.x & 31;
    if (lid == 0) { smn[wid] = mn; smx[wid] = mx; }
    __syncthreads();
    if (threadIdx.x == 0) {
        unsigned bmn = smn[0], bmx = smx[0];
        #pragma unroll
        for (int i = 1; i < 8; i++) { bmn = min(bmn, smn[i]); bmx = max(bmx, smx[i]); }
        g_pmin[blockIdx.x] = bmn;   // unconditional -> no init kernel
        g_pmax[blockIdx.x] = bmx;
    }
    // PDL: allow dependent (ssim) kernel to start; prior global writes are
    // visible to dependents after their griddepcontrol.wait.
    asm volatile("griddepcontrol.launch_dependents;" ::: "memory");
}

struct HAcc { float f0[4], f1[4], f2[4], f3[4], f4[4]; };

__device__ __forceinline__ void consume(HAcc& s, int e, float a, float b) {
    float aa = a * a, bb = b * b, ab = a * b;
    #pragma unroll
    for (int j = 0; j < 4; j++) {
        int k = e - 3 - j;           // tap index for output j
        if (k >= 0 && k < WS) {
            float w = wk_of(k);
            s.f0[j] = fmaf(w, a,  s.f0[j]);
            s.f1[j] = fmaf(w, b,  s.f1[j]);
            s.f2[j] = fmaf(w, aa, s.f2[j]);
            s.f3[j] = fmaf(w, bb, s.f3[j]);
            s.f4[j] = fmaf(w, ab, s.f4[j]);
        }
    }
}

// Horizontal pass for one item: 4 outputs (cols c0..c0+3 of the tile) on tile
// row r, reading img directly from global (no smem staging).
__device__ __forceinline__ void hproc(
    int r, int c0, int x0, int y0,
    const float* __restrict__ p1, const float* __restrict__ p2,
    bool interior, float (&h)[5][TW][TS])
{
    HAcc s;
    #pragma unroll
    for (int j = 0; j < 4; j++) {
        s.f0[j] = 0.f; s.f1[j] = 0.f; s.f2[j] = 0.f; s.f3[j] = 0.f; s.f4[j] = 0.f;
    }
    const int gy = y0 + r - HALO;
    // needed cols: e = 3..16 where global col = x0 + c0 - 8 + e
    if (interior) {
        const float4* r1 = (const float4*)(p1 + (long)gy * IMG_W + (x0 + c0 - 8));
        const float4* r2 = (const float4*)(p2 + (long)gy * IMG_W + (x0 + c0 - 8));
        #pragma unroll
        for (int t = 0; t < 5; t++) {
            float4 va = __ldg(r1 + t);
            float4 vb = __ldg(r2 + t);
            const int e = 4 * t;
            if (e + 0 >= 3 && e + 0 <= 16) consume(s, e + 0, va.x, vb.x);
            if (e + 1 >= 3 && e + 1 <= 16) consume(s, e + 1, va.y, vb.y);
            if (e + 2 >= 3 && e + 2 <= 16) consume(s, e + 2, va.z, vb.z);
            if (e + 3 >= 3 && e + 3 <= 16) consume(s, e + 3, va.w, vb.w);
        }
    } else {
        const bool yok = (gy >= 0) & (gy < IMG_H);
        const float* b1 = p1 + (long)gy * IMG_W;
        const float* b2 = p2 + (long)gy * IMG_W;
        #pragma unroll
        for (int e = 3; e <= 16; e++) {
            int gx = x0 + c0 - 8 + e;
            bool ok = yok & (gx >= 0) & (gx < IMG_W);
            float a = 0.f, b = 0.f;
            if (ok) { a = __ldg(b1 + gx); b = __ldg(b2 + gx); }
            consume(s, e, a, b);
        }
    }
    *(float4*)&h[0][r][c0] = make_float4(s.f0[0], s.f0[1], s.f0[2], s.f0[3]);
    *(float4*)&h[1][r][c0] = make_float4(s.f1[0], s.f1[1], s.f1[2], s.f1[3]);
    *(float4*)&h[2][r][c0] = make_float4(s.f2[0], s.f2[1], s.f2[2], s.f2[3]);
    *(float4*)&h[3][r][c0] = make_float4(s.f3[0], s.f3[1], s.f3[2], s.f3[3]);
    *(float4*)&h[4][r][c0] = make_float4(s.f4[0], s.f4[1], s.f4[2], s.f4[3]);
}

__global__ __launch_bounds__(256, 5)
void ssim_kernel(const float* __restrict__ img1, const float* __restrict__ img2,
                 float* __restrict__ out) {
    __shared__ float h[5][TW][TS];
    __shared__ unsigned red_mn[8], red_mx[8];

    const int n = blockIdx.z;
    const int x0 = blockIdx.x * TS;
    const int y0 = blockIdx.y * TS;
    const int tid = threadIdx.x;

    const float* p1 = img1 + (size_t)n * IMG_H * IMG_W;
    const float* p2 = img2 + (size_t)n * IMG_H * IMG_W;

    // interior <=> all vector-load addresses in [0, 512) rows/cols
    const bool interior = (x0 != 0) & (x0 != IMG_W - TS) &
                          (y0 != 0) & (y0 != IMG_H - TS);

    // ---- horizontal pass straight from global: 336 items, 2 per thread max ----
    {
        int r = tid >> 3;
        int c0 = (tid & 7) << 2;
        hproc(r, c0, x0, y0, p1, p2, interior, h);
        if (tid < 80) hproc(r + 32, c0, x0, y0, p1, p2, interior, h);
    }
    __syncthreads();

    // ---- vertical pass: 4 adjacent output rows per thread ----
    const int tx = tid & 31;
    const int ty0 = (tid >> 5) << 2;   // 0,4,...,28
    float m1[4]  = {0,0,0,0}, m2[4]  = {0,0,0,0};
    float q1[4]  = {0,0,0,0}, q2a[4] = {0,0,0,0}, q12[4] = {0,0,0,0};
    #pragma unroll
    for (int i = 0; i < 14; i++) {
        float v0 = h[0][ty0 + i][tx];
        float v1 = h[1][ty0 + i][tx];
        float v2 = h[2][ty0 + i][tx];
        float v3 = h[3][ty0 + i][tx];
        float v4 = h[4][ty0 + i][tx];
        #pragma unroll
        for (int j = 0; j < 4; j++) {
            int k = i - j;
            if (k >= 0 && k < WS) {
                float w = wk_of(k);
                m1[j]  = fmaf(w, v0, m1[j]);
                m2[j]  = fmaf(w, v1, m2[j]);
                q1[j]  = fmaf(w, v2, q1[j]);
                q2a[j] = fmaf(w, v3, q2a[j]);
                q12[j] = fmaf(w, v4, q12[j]);
            }
        }
    }

    // ---- PDL: minmax results only needed from here on ----
    asm volatile("griddepcontrol.wait;" ::: "memory");
    {
        unsigned mn = min(g_pmin[tid], g_pmin[tid + 256]);
        unsigned mx = max(g_pmax[tid], g_pmax[tid + 256]);
        #pragma unroll
        for (int off = 16; off > 0; off >>= 1) {
            mn = min(mn, __shfl_xor_sync(0xFFFFFFFFu, mn, off));
            mx = max(mx, __shfl_xor_sync(0xFFFFFFFFu, mx, off));
        }
        if ((tid & 31) == 0) { red_mn[tid >> 5] = mn; red_mx[tid >> 5] = mx; }
    }
    __syncthreads();

    float C1, C2;
    {
        unsigned bmn = red_mn[0], bmx = red_mx[0];
        #pragma unroll
        for (int i = 1; i < 8; i++) { bmn = min(bmn, red_mn[i]); bmx = max(bmx, red_mx[i]); }
        float L = decf(bmx) - decf(bmn);
        if (L == 0.f) L = 5.f;
        C1 = (0.01f * L) * (0.01f * L);
        C2 = (0.03f * L) * (0.03f * L);
    }

    float* po = out + (size_t)n * IMG_H * IMG_W;
    #pragma unroll
    for (int j = 0; j < 4; j++) {
        float mu1_sq = m1[j] * m1[j];
        float mu2_sq = m2[j] * m2[j];
        float mu1mu2 = m1[j] * m2[j];
        float sig1  = q1[j]  - mu1_sq;
        float sig2  = q2a[j] - mu2_sq;
        float sig12 = q12[j] - mu1mu2;
        float num = (2.f * mu1mu2 + C1) * (2.f * sig12 + C2);
        float den = (mu1_sq + mu2_sq + C1) * (sig1 + sig2 + C2);
        po[(size_t)(y0 + ty0 + j) * IMG_W + (x0 + tx)] = __fdividef(num, den);
    }
}

extern "C" void kernel_launch(void* const* d_in, const int* in_sizes, int n_in,
                              void* d_out, int out_size) {
    const float* img1 = (const float*)d_in[0];
    const float* img2 = (const float*)d_in[1];
    float* out = (float*)d_out;

    int n_elems = N_IMG * IMG_H * IMG_W;
    minmax_kernel<<<NPART, 256>>>(img1, n_elems / 4);

    // ssim launched with programmatic stream serialization: it may begin
    // while minmax is still running; it only waits (griddepcontrol.wait)
    // right before reading the minmax partials in its epilogue.
    cudaLaunchConfig_t cfg = {};
    cfg.gridDim = dim3(IMG_W / TS, IMG_H / TS, N_IMG);
    cfg.blockDim = dim3(256, 1, 1);
    cfg.dynamicSmemBytes = 0;
    cfg.stream = 0;
    cudaLaunchAttribute at[1];
    at[0].id = cudaLaunchAttributeProgrammaticStreamSerialization;
    at[0].val.programmaticStreamSerializationAllowed = 1;
    cfg.attrs = at;
    cfg.numAttrs = 1;
    cudaLaunchKernelEx(&cfg, ssim_kernel, img1, img2, out);
}